// round 8
// baseline (speedup 1.0000x reference)
#include <cuda_runtime.h>
#include <cuda_bf16.h>
#include <cstdint>

// LabelClusterLoss over E[C0=512, T=128, C1=1024] fp32 -> scalar, one launch.
// Accumulators: A_sq = sum(E^2); A_R2 = sum_rows(rowsum^2);
//               A_C2 = sum_cols(colsum^2); A_T2 = sum_t(slicesum^2).
//
// TMA bulk-copy pipeline: LDG variants cap at 5.6 TB/s (per-SM L1tex wavefront
// queue limits in-flight bytes to ~31KB/SM). cp.async.bulk bypasses that queue:
// producer warp streams 4KB rows into an 8-stage SMEM ring (2 stages per
// consumer warp); consumer warps do identical math from SMEM.
//
// Grid = 1024 blocks x 160 thr (4 consumer warps + 1 producer warp).
// Block b -> (t = b>>3, seg = b&7, rows seg*64..+63); consumer warp w gets
// rows 4k+w. Election tail: last-of-8 per t combines, last of 128 computes
// the loss. Counters self-reset -> deterministic across graph replays.

#define T_DIM 128
#define C0_DIM 512
#define C1_DIM 1024
#define NSEG 8
#define NBLK (T_DIM * NSEG)
#define NTHR 160
#define ROW_BYTES 4096

__device__ float         p_cs[NBLK][C1_DIM];   // per-(t,seg) colsum partials (4 MB)
__device__ float         p_sr[NBLK][2];        // per-(t,seg) {sq, r2}
__device__ double        p_t4[T_DIM][4];       // per-t {sq, r2, cs2, cs^2}
__device__ unsigned int  p_tcnt[T_DIM];        // zero at load; self-reset
__device__ unsigned int  p_gcnt;               // zero at load; self-reset

__device__ __forceinline__ uint32_t smem_u32(const void* p) {
    uint32_t a;
    asm("{ .reg .u64 t; cvta.to.shared.u64 t, %1; cvt.u32.u64 %0, t; }"
        : "=r"(a) : "l"(p));
    return a;
}
__device__ __forceinline__ void mb_init(uint32_t m, uint32_t cnt) {
    asm volatile("mbarrier.init.shared.b64 [%0], %1;" :: "r"(m), "r"(cnt) : "memory");
}
__device__ __forceinline__ void mb_expect_tx(uint32_t m, uint32_t tx) {
    asm volatile("mbarrier.arrive.expect_tx.shared.b64 _, [%0], %1;"
                 :: "r"(m), "r"(tx) : "memory");
}
__device__ __forceinline__ void mb_arrive(uint32_t m) {
    asm volatile("mbarrier.arrive.shared.b64 _, [%0];" :: "r"(m) : "memory");
}
__device__ __forceinline__ void mb_wait(uint32_t m, uint32_t parity) {
    asm volatile(
        "{\n\t.reg .pred P;\n"
        "WL%=:\n\t"
        "mbarrier.try_wait.parity.acquire.cta.shared::cta.b64 P, [%0], %1, 0x989680;\n\t"
        "@!P bra WL%=;\n\t}"
        :: "r"(m), "r"(parity) : "memory");
}
__device__ __forceinline__ void tma_g2s(uint32_t dst, const void* src,
                                        uint32_t bytes, uint32_t m) {
    asm volatile(
        "cp.async.bulk.shared::cta.global.mbarrier::complete_tx::bytes [%0], [%1], %2, [%3];"
        :: "r"(dst), "l"(src), "r"(bytes), "r"(m) : "memory");
}

__global__ void __launch_bounds__(NTHR, 6)
lcl_bulk_kernel(const float* __restrict__ A, float* __restrict__ out) {
    const int b    = blockIdx.x;
    const int t    = b >> 3;
    const int seg  = b & 7;
    const int tid  = threadIdx.x;
    const int w    = tid >> 5;          // 0..3 consumers, 4 producer
    const int lane = tid & 31;

    // 8 stages of 4KB: stages (2w, 2w+1) belong to consumer warp w.
    __shared__ __align__(1024) float stage[8][1024];
    __shared__ __align__(8) unsigned long long mb_full[8];
    __shared__ __align__(8) unsigned long long mb_empty[8];
    __shared__ float red_a[4];
    __shared__ float red_b[4];
    __shared__ bool  s_comb;
    __shared__ bool  s_final;

    if (tid == 0) {
#pragma unroll
        for (int s = 0; s < 8; s++) {
            mb_init(smem_u32(&mb_full[s]), 1);    // completed by TMA tx
            mb_init(smem_u32(&mb_empty[s]), 1);   // completed by consumer lane 0
        }
        asm volatile("fence.proxy.async.shared::cta;" ::: "memory");
    }
    __syncthreads();

    // ===================== producer warp: stream 64 rows =====================
    if (w == 4 && lane == 0) {
        const char* base =
            reinterpret_cast<const char*>(A) +
            ((size_t)(seg * 64) * T_DIM + t) * (size_t)C1_DIM * 4;
        const size_t row_stride = (size_t)T_DIM * C1_DIM * 4;   // 512 KB
        for (int k = 0; k < 16; k++) {
            const int par_e = ((k >> 1) - 1) & 1;
#pragma unroll
            for (int ww = 0; ww < 4; ww++) {
                const int sidx = ww * 2 + (k & 1);
                if (k >= 2) mb_wait(smem_u32(&mb_empty[sidx]), par_e);
                const uint32_t fm = smem_u32(&mb_full[sidx]);
                mb_expect_tx(fm, ROW_BYTES);
                tma_g2s(smem_u32(&stage[sidx][0]),
                        base + (size_t)(4 * k + ww) * row_stride, ROW_BYTES, fm);
            }
        }
    }

    // ===================== consumer warps: math from SMEM ====================
    float cs0[16], cs1[16];
#pragma unroll
    for (int q = 0; q < 16; q++) { cs0[q] = 0.0f; cs1[q] = 0.0f; }
    float sq_acc = 0.0f;
    float r2_acc = 0.0f;     // lane 0

    if (w < 4) {
        const uint32_t mfull0 = smem_u32(&mb_full[w * 2]);
        const uint32_t mfull1 = smem_u32(&mb_full[w * 2 + 1]);
        const uint32_t mempty0 = smem_u32(&mb_empty[w * 2]);
        const uint32_t mempty1 = smem_u32(&mb_empty[w * 2 + 1]);
        for (int k = 0; k < 16; k++) {
            const int odd = k & 1;
            mb_wait(odd ? mfull1 : mfull0, (k >> 1) & 1);
            const float4* rowp =
                reinterpret_cast<const float4*>(&stage[w * 2 + odd][0]) + lane;
            float rs = 0.0f;
#pragma unroll
            for (int p = 0; p < 8; p++) {
                float4 v = rowp[p * 32];          // conflict-free LDS.128
                sq_acc = fmaf(v.x, v.x, sq_acc);
                sq_acc = fmaf(v.y, v.y, sq_acc);
                sq_acc = fmaf(v.z, v.z, sq_acc);
                sq_acc = fmaf(v.w, v.w, sq_acc);
                if (p < 4) {
                    cs0[p * 4 + 0] += v.x; cs0[p * 4 + 1] += v.y;
                    cs0[p * 4 + 2] += v.z; cs0[p * 4 + 3] += v.w;
                } else {
                    cs1[(p - 4) * 4 + 0] += v.x; cs1[(p - 4) * 4 + 1] += v.y;
                    cs1[(p - 4) * 4 + 2] += v.z; cs1[(p - 4) * 4 + 3] += v.w;
                }
                rs += (v.x + v.y) + (v.z + v.w);
            }
#pragma unroll
            for (int o = 16; o > 0; o >>= 1) rs += __shfl_xor_sync(0xFFFFFFFFu, rs, o);
            if (lane == 0) r2_acc = fmaf(rs, rs, r2_acc);
            __syncwarp();
            if (lane == 0) mb_arrive(odd ? mempty1 : mempty0);
        }
    }
    __syncthreads();   // all stages consumed; stage[] reusable as scratch

    // ============ cross-warp colsum reduce: 4 warps -> warp 0 ============
    float* sbuf = &stage[0][0];
    if (w == 2 || w == 3) {
        float* dp = &sbuf[(w - 2) * 1024];
#pragma unroll
        for (int p = 0; p < 4; p++) {
            reinterpret_cast<float4*>(dp)[p * 32 + lane] =
                make_float4(cs0[p*4+0], cs0[p*4+1], cs0[p*4+2], cs0[p*4+3]);
            reinterpret_cast<float4*>(dp)[(p + 4) * 32 + lane] =
                make_float4(cs1[p*4+0], cs1[p*4+1], cs1[p*4+2], cs1[p*4+3]);
        }
    }
    __syncthreads();
    if (w < 2) {
        const float* sp = &sbuf[w * 1024];
#pragma unroll
        for (int p = 0; p < 4; p++) {
            float4 u = reinterpret_cast<const float4*>(sp)[p * 32 + lane];
            cs0[p*4+0] += u.x; cs0[p*4+1] += u.y; cs0[p*4+2] += u.z; cs0[p*4+3] += u.w;
            float4 v = reinterpret_cast<const float4*>(sp)[(p + 4) * 32 + lane];
            cs1[p*4+0] += v.x; cs1[p*4+1] += v.y; cs1[p*4+2] += v.z; cs1[p*4+3] += v.w;
        }
    }
    __syncthreads();
    if (w == 1) {
        float* dp = &sbuf[0];
#pragma unroll
        for (int p = 0; p < 4; p++) {
            reinterpret_cast<float4*>(dp)[p * 32 + lane] =
                make_float4(cs0[p*4+0], cs0[p*4+1], cs0[p*4+2], cs0[p*4+3]);
            reinterpret_cast<float4*>(dp)[(p + 4) * 32 + lane] =
                make_float4(cs1[p*4+0], cs1[p*4+1], cs1[p*4+2], cs1[p*4+3]);
        }
    }
    __syncthreads();
    if (w == 0) {
        const float* sp = &sbuf[0];
#pragma unroll
        for (int p = 0; p < 4; p++) {
            float4 u = reinterpret_cast<const float4*>(sp)[p * 32 + lane];
            cs0[p*4+0] += u.x; cs0[p*4+1] += u.y; cs0[p*4+2] += u.z; cs0[p*4+3] += u.w;
            float4 v = reinterpret_cast<const float4*>(sp)[(p + 4) * 32 + lane];
            cs1[p*4+0] += v.x; cs1[p*4+1] += v.y; cs1[p*4+2] += v.z; cs1[p*4+3] += v.w;
        }
    }

    // ==================== block totals of sq / r2 ====================
    if (w < 4) {
        float s = sq_acc;
#pragma unroll
        for (int o = 16; o > 0; o >>= 1) s += __shfl_xor_sync(0xFFFFFFFFu, s, o);
        if (lane == 0) { red_a[w] = s; red_b[w] = r2_acc; }
    }
    __syncthreads();

    if (w == 0) {
        if (lane == 0) {
            p_sr[b][0] = red_a[0] + red_a[1] + red_a[2] + red_a[3];
            p_sr[b][1] = red_b[0] + red_b[1] + red_b[2] + red_b[3];
        }
        float4* dst = reinterpret_cast<float4*>(&p_cs[b][0]);
#pragma unroll
        for (int p = 0; p < 4; p++) {
            dst[p * 32 + lane] =
                make_float4(cs0[p*4+0], cs0[p*4+1], cs0[p*4+2], cs0[p*4+3]);
            dst[(p + 4) * 32 + lane] =
                make_float4(cs1[p*4+0], cs1[p*4+1], cs1[p*4+2], cs1[p*4+3]);
        }
    }

    // ============ elect last finisher for this t (no waiting) ============
    __syncthreads();
    if (tid == 0) {
        s_final = false;
        __threadfence();
        unsigned old = atomicAdd(&p_tcnt[t], 1);
        s_comb = (old == NSEG - 1);
    }
    __syncthreads();

    if (s_comb) {
        __threadfence();
        float4 f0 = make_float4(0.f, 0.f, 0.f, 0.f);
        float4 f1 = make_float4(0.f, 0.f, 0.f, 0.f);
        if (tid < 128) {
#pragma unroll
            for (int s = 0; s < NSEG; s++) {
                const float4* p =
                    reinterpret_cast<const float4*>(&p_cs[t * NSEG + s][tid * 8]);
                float4 u0 = __ldcg(p + 0);
                float4 u1 = __ldcg(p + 1);
                f0.x += u0.x; f0.y += u0.y; f0.z += u0.z; f0.w += u0.w;
                f1.x += u1.x; f1.y += u1.y; f1.z += u1.z; f1.w += u1.w;
            }
        }
        float cs  = ((f0.x + f0.y) + (f0.z + f0.w)) + ((f1.x + f1.y) + (f1.z + f1.w));
        float cs2 = f0.x*f0.x + f0.y*f0.y + f0.z*f0.z + f0.w*f0.w
                  + f1.x*f1.x + f1.y*f1.y + f1.z*f1.z + f1.w*f1.w;
        if (tid < 128) {
#pragma unroll
            for (int o = 16; o > 0; o >>= 1) {
                cs  += __shfl_xor_sync(0xFFFFFFFFu, cs,  o);
                cs2 += __shfl_xor_sync(0xFFFFFFFFu, cs2, o);
            }
            if (lane == 0) { red_a[w] = cs; red_b[w] = cs2; }
        }
        __syncthreads();
        if (tid == 0) {
            float tcs  = red_a[0] + red_a[1] + red_a[2] + red_a[3];
            float tcs2 = red_b[0] + red_b[1] + red_b[2] + red_b[3];
            double sq_t = 0.0, r2_t = 0.0;
#pragma unroll
            for (int s = 0; s < NSEG; s++) {
                sq_t += (double)__ldcg(&p_sr[t * NSEG + s][0]);
                r2_t += (double)__ldcg(&p_sr[t * NSEG + s][1]);
            }
            p_t4[t][0] = sq_t;
            p_t4[t][1] = r2_t;
            p_t4[t][2] = (double)tcs2;
            p_t4[t][3] = (double)tcs * (double)tcs;
            p_tcnt[t] = 0;                       // self-reset
            __threadfence();
            unsigned o2 = atomicAdd(&p_gcnt, 1);
            if (o2 == T_DIM - 1) s_final = true;
        }
    }
    __syncthreads();

    // ================= last combiner computes the loss =================
    if (s_final && w == 0) {
        __threadfence();
        double a0 = 0, a1 = 0, a2 = 0, a3 = 0;
#pragma unroll
        for (int q = 0; q < 4; q++) {
            int tt = lane + 32 * q;
            a0 += __ldcg(&p_t4[tt][0]);
            a1 += __ldcg(&p_t4[tt][1]);
            a2 += __ldcg(&p_t4[tt][2]);
            a3 += __ldcg(&p_t4[tt][3]);
        }
#pragma unroll
        for (int o = 16; o > 0; o >>= 1) {
            a0 += __shfl_xor_sync(0xFFFFFFFFu, a0, o);
            a1 += __shfl_xor_sync(0xFFFFFFFFu, a1, o);
            a2 += __shfl_xor_sync(0xFFFFFFFFu, a2, o);
            a3 += __shfl_xor_sync(0xFFFFFFFFu, a3, o);
        }
        if (lane == 0) {
            const double c0 = (double)C0_DIM, c1 = (double)C1_DIM;
            const double cross  = a3 / (c0 * c1);
            const double intra  = a0 - a1 / c1;
            const double inter  = a1 / c1 - cross;
            const double dintra = a0 - a2 / c0;
            const double dinter = a2 / c0 - cross;
            out[0] = (float)(0.5 * (intra / inter + dintra / dinter) / (c0 * c1));
            p_gcnt = 0;                          // self-reset
        }
    }
}

extern "C" void kernel_launch(void* const* d_in, const int* in_sizes, int n_in,
                              void* d_out, int out_size) {
    const float* A = (const float*)d_in[0];
    float* out = (float*)d_out;
    (void)in_sizes; (void)n_in; (void)out_size;

    lcl_bulk_kernel<<<NBLK, NTHR>>>(A, out);
}